// round 16
// baseline (speedup 1.0000x reference)
#include <cuda_runtime.h>

#define N_AGENTS 11
#define OBS_DIM 115
#define GS_DIM (N_AGENTS * OBS_DIM)   // 1265
#define ID_LO 97
#define FULL 0xFFFFFFFFu
#define WPB 4                          // warps per block; 2 rows per warp

__global__ __launch_bounds__(128, 16)
void qllmmixer_kernel(const float* __restrict__ q,        // [B, 11]
                      const float* __restrict__ gs,       // [B, 1265]
                      float* __restrict__ out,            // [B]
                      int B)
{
    // Two 121-float id-window tiles per warp (rows r0, r1).
    __shared__ float tile[WPB][2][128];

    const int wb    = threadIdx.x >> 5;
    const int lane  = threadIdx.x & 31;
    const int halfw = lane >> 4;        // which of the 2 rows this half-warp reduces
    const int sub   = lane & 15;

    const long long r0 = ((long long)blockIdx.x * WPB + wb) * 2;
    const long long r1 = r0 + 1;
    if (r0 >= B) return;                // B is a multiple of 8 -> r1 valid too

    const float POS_INF = __int_as_float(0x7f800000);
    const float NEG_INF = __int_as_float(0xff800000);

    const float* grow0 = gs + r0 * GS_DIM;
    const float* grow1 = gs + r1 * GS_DIM;

    // ---- Issue the big-latency loads FIRST: both rows' id-window tiles.
    // 8 independent LDGs, coalesced within each 44B window (~5 lines each).
    #pragma unroll
    for (int i = 0; i < 8; ++i) {
        const int t = lane + 32 * i;          // 0..255
        const int r = t >> 7;                 // 0: row0, 1: row1
        const int u = t & 127;
        if (u < N_AGENTS * N_AGENTS) {
            const int a = u / N_AGENTS;
            const int k = u - a * N_AGENTS;
            const float* g = r ? grow1 : grow0;
            tile[wb][r][u] = __ldcs(g + a * OBS_DIM + ID_LO + k);
        }
    }

    // ---- Fill the latency shadow with the independent small loads.
    const float bx0 = __ldg(grow0 + 88), by0 = __ldg(grow0 + 89), tm0 = __ldg(grow0 + 95);
    const float bx1 = __ldg(grow1 + 88), by1 = __ldg(grow1 + 89), tm1 = __ldg(grow1 + 95);

    float qa = 0.0f;
    if (sub < N_AGENTS)
        qa = __ldg(q + (halfw ? r1 : r0) * N_AGENTS + sub);

    __syncwarp();

    // ---- Per-agent argmax: row0 on lanes 0..10, row1 on lanes 16..26 (parallel).
    int bid = 0;
    if (sub < N_AGENTS) {
        const float* tp = &tile[wb][halfw][sub * N_AGENTS];
        float best = tp[0];
        #pragma unroll
        for (int k = 1; k < N_AGENTS; ++k) {
            const float v = tp[k];
            if (v > best) { best = v; bid = k; }   // strict '>' = first-max
        }
    }

    // ---- Dependent pos gathers: both rows issued back-to-back.
    const int pa   = lane >> 1;                          // agent 0..15
    const int half = lane & 1;
    const int bid0 = __shfl_sync(FULL, bid, pa);         // row0 bids on lanes 0..10
    const int bid1 = __shfl_sync(FULL, bid, 16 + pa);    // row1 bids on lanes 16..26
    float posv0 = 0.0f, posv1 = 0.0f;
    if (lane < 2 * N_AGENTS) {
        posv0 = __ldcs(grow0 + pa * OBS_DIM + 2 * bid0 + half);
        posv1 = __ldcs(grow1 + pa * OBS_DIM + 2 * bid1 + half);
    }

    // Route (px, py) of agent `sub` of this half's row to this lane.
    const float pxA = __shfl_sync(FULL, posv0, 2 * sub);
    const float pyA = __shfl_sync(FULL, posv0, 2 * sub + 1);
    const float pxB = __shfl_sync(FULL, posv1, 2 * sub);
    const float pyB = __shfl_sync(FULL, posv1, 2 * sub + 1);
    const float px = halfw ? pxB : pxA;
    const float py = halfw ? pyB : pyA;

    // Per-half row scalars
    const float bx = halfw ? bx1 : bx0;
    const float by = halfw ? by1 : by0;
    const float tm = halfw ? tm1 : tm0;
    const float dxg = bx - 1.0f;
    const float bgd = sqrtf(dxg * dxg + by * by);
    const bool valid = (tm != 0.0f) && (bgd > 0.19f) && (bgd < 0.99f);

    // ---- Per-agent math
    float dist = POS_INF;
    float gd   = 0.0f;
    int   aidx = 64;
    if (sub < N_AGENTS) {
        const float dxb = px - bx;
        const float dyb = py - by;
        dist = sqrtf(dxb * dxb + dyb * dyb);
        const float dxgl = px - 1.0f;
        gd = sqrtf(dxgl * dxgl + py * py);
        aidx = sub;
    }

    // ---- half-warp argmin (first-index tie-break, jnp.argmin)
    float mval = dist;
    int   midx = aidx;
    #pragma unroll
    for (int off = 8; off > 0; off >>= 1) {
        const float ov = __shfl_xor_sync(FULL, mval, off);
        const int   oi = __shfl_xor_sync(FULL, midx, off);
        if (ov < mval || (ov == mval && oi < midx)) { mval = ov; midx = oi; }
    }

    // ---- combined + half-warp softmax
    float combined = NEG_INF;
    if (sub < N_AGENTS) {
        if (valid) combined = (aidx == midx) ? 5.0f : 0.0f;
        else       combined = 1.0f / (gd + 1e-6f);
    }

    float m = combined;
    #pragma unroll
    for (int off = 8; off > 0; off >>= 1)
        m = fmaxf(m, __shfl_xor_sync(FULL, m, off));

    const float e = (sub < N_AGENTS) ? expf(combined - m) : 0.0f;

    float s  = e;
    float qe = qa * e;
    #pragma unroll
    for (int off = 8; off > 0; off >>= 1) {
        s  += __shfl_xor_sync(FULL, s,  off);
        qe += __shfl_xor_sync(FULL, qe, off);
    }

    if (sub == 0)
        out[halfw ? r1 : r0] = (qe / s) * (float)N_AGENTS;
}

extern "C" void kernel_launch(void* const* d_in, const int* in_sizes, int n_in,
                              void* d_out, int out_size)
{
    const float* q  = (const float*)d_in[0];   // agents_q  [128,512,11]
    const float* gs = (const float*)d_in[1];   // global_state [128,512,1265]
    float* out = (float*)d_out;

    const int B = in_sizes[0] / N_AGENTS;      // 65536 rows

    const int rows_per_block = WPB * 2;        // 8
    const int blocks = (B + rows_per_block - 1) / rows_per_block;

    qllmmixer_kernel<<<blocks, 32 * WPB>>>(q, gs, out, B);
}

// round 17
// speedup vs baseline: 1.0779x; 1.0779x over previous
#include <cuda_runtime.h>

#define N_AGENTS 11
#define OBS_DIM 115
#define GS_DIM (N_AGENTS * OBS_DIM)   // 1265
#define ID_LO 97
#define FULL 0xFFFFFFFFu
#define WPB 4                          // warps per block; 2 rows per warp

__global__ __launch_bounds__(128, 16)
void qllmmixer_kernel(const float* __restrict__ q,        // [B, 11]
                      const float* __restrict__ gs,       // [B, 1265]
                      float* __restrict__ out,            // [B]
                      int B)
{
    // Two 121-float id-window tiles per warp (rows r0, r1).
    __shared__ float tile[WPB][2][128];

    const int wb    = threadIdx.x >> 5;
    const int lane  = threadIdx.x & 31;
    const int halfw = lane >> 4;        // which of the 2 rows this half-warp reduces
    const int sub   = lane & 15;

    const long long r0 = ((long long)blockIdx.x * WPB + wb) * 2;
    const long long r1 = r0 + 1;
    if (r0 >= B) return;                // B is a multiple of 8 -> r1 valid too

    const float POS_INF = __int_as_float(0x7f800000);
    const float NEG_INF = __int_as_float(0xff800000);

    const float* grow0 = gs + r0 * GS_DIM;
    const float* grow1 = gs + r1 * GS_DIM;

    // ---- Issue the big-latency loads FIRST: both rows' id-window tiles.
    // DEFAULT caching (__ldg, not __ldcs): the tail 128B line of agent a's id
    // window overlaps agent a+1's pos region (460B agent stride, 28B gap), so
    // keeping these lines L2-resident turns a fraction of the later dependent
    // pos gathers into L2 hits instead of fresh DRAM granules.
    #pragma unroll
    for (int i = 0; i < 8; ++i) {
        const int t = lane + 32 * i;          // 0..255
        const int r = t >> 7;                 // 0: row0, 1: row1
        const int u = t & 127;
        if (u < N_AGENTS * N_AGENTS) {
            const int a = u / N_AGENTS;
            const int k = u - a * N_AGENTS;
            const float* g = r ? grow1 : grow0;
            tile[wb][r][u] = __ldg(g + a * OBS_DIM + ID_LO + k);
        }
    }

    // ---- Fill the latency shadow with the independent small loads.
    const float bx0 = __ldg(grow0 + 88), by0 = __ldg(grow0 + 89), tm0 = __ldg(grow0 + 95);
    const float bx1 = __ldg(grow1 + 88), by1 = __ldg(grow1 + 89), tm1 = __ldg(grow1 + 95);

    float qa = 0.0f;
    if (sub < N_AGENTS)
        qa = __ldg(q + (halfw ? r1 : r0) * N_AGENTS + sub);

    __syncwarp();

    // ---- Per-agent argmax: row0 on lanes 0..10, row1 on lanes 16..26 (parallel).
    int bid = 0;
    if (sub < N_AGENTS) {
        const float* tp = &tile[wb][halfw][sub * N_AGENTS];
        float best = tp[0];
        #pragma unroll
        for (int k = 1; k < N_AGENTS; ++k) {
            const float v = tp[k];
            if (v > best) { best = v; bid = k; }   // strict '>' = first-max
        }
    }

    // ---- Dependent pos gathers: both rows issued back-to-back.
    // __ldcs here: true last use of these lines.
    const int pa   = lane >> 1;                          // agent 0..15
    const int half = lane & 1;
    const int bid0 = __shfl_sync(FULL, bid, pa);         // row0 bids on lanes 0..10
    const int bid1 = __shfl_sync(FULL, bid, 16 + pa);    // row1 bids on lanes 16..26
    float posv0 = 0.0f, posv1 = 0.0f;
    if (lane < 2 * N_AGENTS) {
        posv0 = __ldcs(grow0 + pa * OBS_DIM + 2 * bid0 + half);
        posv1 = __ldcs(grow1 + pa * OBS_DIM + 2 * bid1 + half);
    }

    // Route (px, py) of agent `sub` of this half's row to this lane.
    const float pxA = __shfl_sync(FULL, posv0, 2 * sub);
    const float pyA = __shfl_sync(FULL, posv0, 2 * sub + 1);
    const float pxB = __shfl_sync(FULL, posv1, 2 * sub);
    const float pyB = __shfl_sync(FULL, posv1, 2 * sub + 1);
    const float px = halfw ? pxB : pxA;
    const float py = halfw ? pyB : pyA;

    // Per-half row scalars
    const float bx = halfw ? bx1 : bx0;
    const float by = halfw ? by1 : by0;
    const float tm = halfw ? tm1 : tm0;
    const float dxg = bx - 1.0f;
    const float bgd = sqrtf(dxg * dxg + by * by);
    const bool valid = (tm != 0.0f) && (bgd > 0.19f) && (bgd < 0.99f);

    // ---- Per-agent math
    float dist = POS_INF;
    float gd   = 0.0f;
    int   aidx = 64;
    if (sub < N_AGENTS) {
        const float dxb = px - bx;
        const float dyb = py - by;
        dist = sqrtf(dxb * dxb + dyb * dyb);
        const float dxgl = px - 1.0f;
        gd = sqrtf(dxgl * dxgl + py * py);
        aidx = sub;
    }

    // ---- half-warp argmin (first-index tie-break, jnp.argmin)
    float mval = dist;
    int   midx = aidx;
    #pragma unroll
    for (int off = 8; off > 0; off >>= 1) {
        const float ov = __shfl_xor_sync(FULL, mval, off);
        const int   oi = __shfl_xor_sync(FULL, midx, off);
        if (ov < mval || (ov == mval && oi < midx)) { mval = ov; midx = oi; }
    }

    // ---- combined + half-warp softmax
    float combined = NEG_INF;
    if (sub < N_AGENTS) {
        if (valid) combined = (aidx == midx) ? 5.0f : 0.0f;
        else       combined = 1.0f / (gd + 1e-6f);
    }

    float m = combined;
    #pragma unroll
    for (int off = 8; off > 0; off >>= 1)
        m = fmaxf(m, __shfl_xor_sync(FULL, m, off));

    const float e = (sub < N_AGENTS) ? expf(combined - m) : 0.0f;

    float s  = e;
    float qe = qa * e;
    #pragma unroll
    for (int off = 8; off > 0; off >>= 1) {
        s  += __shfl_xor_sync(FULL, s,  off);
        qe += __shfl_xor_sync(FULL, qe, off);
    }

    if (sub == 0)
        out[halfw ? r1 : r0] = (qe / s) * (float)N_AGENTS;
}

extern "C" void kernel_launch(void* const* d_in, const int* in_sizes, int n_in,
                              void* d_out, int out_size)
{
    const float* q  = (const float*)d_in[0];   // agents_q  [128,512,11]
    const float* gs = (const float*)d_in[1];   // global_state [128,512,1265]
    float* out = (float*)d_out;

    const int B = in_sizes[0] / N_AGENTS;      // 65536 rows

    const int rows_per_block = WPB * 2;        // 8
    const int blocks = (B + rows_per_block - 1) / rows_per_block;

    qllmmixer_kernel<<<blocks, 32 * WPB>>>(q, gs, out, B);
}